// round 6
// baseline (speedup 1.0000x reference)
#include <cuda_runtime.h>
#include <math.h>

// Problem dims (fixed by the reference)
#define B_  512
#define XD  768
#define YD  128
#define H2_ 512
#define NPART 16
#define KS1 4          // gemm1 K-splits (768/4 = 192)
#define KS2 4          // gemm2 K-splits (512/4 = 128)

typedef unsigned long long u64;

// Scratch (no allocations allowed -> __device__ globals)
__device__ float  g_H[2][KS1][B_ * H2_];   // gemm1 raw partials
__device__ float  g_Q[2][KS2][B_ * YD];    // gemm2 raw partials
__device__ double g_SyP [NPART][YD];
__device__ double g_Sy2P[NPART][YD];
__device__ double g_pos_row[B_];
__device__ double g_all_row[B_];
__device__ unsigned int g_ctr = 0;

// ---------------- f32x2 packed-FMA helpers (Blackwell FFMA2) ----------------
__device__ __forceinline__ u64 pack2(float lo, float hi) {
    u64 r; asm("mov.b64 %0, {%1, %2};" : "=l"(r) : "f"(lo), "f"(hi)); return r;
}
__device__ __forceinline__ void fma2(u64 &d, u64 a, u64 b) {
    asm("fma.rn.f32x2 %0, %1, %2, %0;" : "+l"(d) : "l"(a), "l"(b));
}
__device__ __forceinline__ float2 unpack2(u64 v) {
    float2 f; asm("mov.b64 {%0, %1}, %2;" : "=f"(f.x), "=f"(f.y) : "l"(v)); return f;
}

// ---------------------------------------------------------------------------
// Kernel A: blocks 0..511 = GEMM1 K-split partials (X@W1-slice, raw),
//           blocks 512..527 = y column stats.
// 64x64 tile, 128 thr, 4x8 micro via FFMA2. head=b&1, ks=(b>>1)&3, t=b>>3.
// ---------------------------------------------------------------------------
__global__ __launch_bounds__(128) void k_gemm1(
    const float* __restrict__ X,
    const float* __restrict__ Y,
    const float* __restrict__ Wmu,
    const float* __restrict__ Wlv)
{
    const int b = blockIdx.x;

    if (b >= 512) {
        // ---- ystats role ----
        const int p = b - 512;
        const int d = threadIdx.x;   // blockDim=128=YD
        const int j0 = p * (B_ / NPART);
        double sy0 = 0.0, sy1 = 0.0, sy20 = 0.0, sy21 = 0.0;
        #pragma unroll 4
        for (int j = j0; j < j0 + B_ / NPART; j += 2) {
            double v0 = (double)Y[j * YD + d];
            double v1 = (double)Y[(j + 1) * YD + d];
            sy0 += v0; sy20 = fma(v0, v0, sy20);
            sy1 += v1; sy21 = fma(v1, v1, sy21);
        }
        g_SyP [p][d] = sy0 + sy1;
        g_Sy2P[p][d] = sy20 + sy21;
        return;
    }

    // ---- GEMM1 partial role ----
    const int head = b & 1;
    const int ks   = (b >> 1) & 3;
    const int t    = b >> 3;             // 0..63
    const int n0   = (t & 7) * 64;
    const int m0   = (t >> 3) * 64;
    const float* W = head ? Wlv : Wmu;
    float*       P = g_H[head][ks];

    __shared__ __align__(16) u64   As2[16][66];  // [k][m] dup {a,a}, padded
    __shared__ __align__(16) float Bs [16][68];  // [k][n], padded

    const int tid = threadIdx.x;
    const int tx  = tid & 7;             // 8 col-groups of 8
    const int ty  = tid >> 3;            // 16 row-groups of 4

    const int arow = tid >> 1;           // 0..63
    const int ak   = (tid & 1) * 8;      // 0 or 8
    const int brow = tid >> 3;           // 0..15
    const int bcol = (tid & 7) * 8;      // 0..56

    const int kbase = ks * (XD / KS1);   // 192 per split
    const float* Xp = X + (m0 + arow) * XD + kbase + ak;
    const float* Wp = W + (kbase + brow) * H2_ + n0 + bcol;

    u64 acc[4][4] = {};

    float4 a_lo = *(const float4*)(Xp + 0);
    float4 a_hi = *(const float4*)(Xp + 4);
    float4 b_lo = *(const float4*)(Wp + 0);
    float4 b_hi = *(const float4*)(Wp + 4);

    const int k_iters = (XD / KS1) / 16;  // 12
    for (int it = 0; it < k_iters; it++) {
        As2[ak + 0][arow] = pack2(a_lo.x, a_lo.x);
        As2[ak + 1][arow] = pack2(a_lo.y, a_lo.y);
        As2[ak + 2][arow] = pack2(a_lo.z, a_lo.z);
        As2[ak + 3][arow] = pack2(a_lo.w, a_lo.w);
        As2[ak + 4][arow] = pack2(a_hi.x, a_hi.x);
        As2[ak + 5][arow] = pack2(a_hi.y, a_hi.y);
        As2[ak + 6][arow] = pack2(a_hi.z, a_hi.z);
        As2[ak + 7][arow] = pack2(a_hi.w, a_hi.w);
        *(float4*)(&Bs[brow][bcol + 0]) = b_lo;
        *(float4*)(&Bs[brow][bcol + 4]) = b_hi;
        __syncthreads();

        if (it + 1 < k_iters) {
            a_lo = *(const float4*)(Xp + (it + 1) * 16 + 0);
            a_hi = *(const float4*)(Xp + (it + 1) * 16 + 4);
            b_lo = *(const float4*)(Wp + (it + 1) * 16 * H2_ + 0);
            b_hi = *(const float4*)(Wp + (it + 1) * 16 * H2_ + 4);
        }

        #pragma unroll
        for (int kk = 0; kk < 16; kk++) {
            ulonglong2 a01 = *(const ulonglong2*)(&As2[kk][ty * 4 + 0]);
            ulonglong2 a23 = *(const ulonglong2*)(&As2[kk][ty * 4 + 2]);
            ulonglong2 b01 = *(const ulonglong2*)(&Bs[kk][tx * 8 + 0]);
            ulonglong2 b23 = *(const ulonglong2*)(&Bs[kk][tx * 8 + 4]);
            fma2(acc[0][0], a01.x, b01.x); fma2(acc[0][1], a01.x, b01.y);
            fma2(acc[0][2], a01.x, b23.x); fma2(acc[0][3], a01.x, b23.y);
            fma2(acc[1][0], a01.y, b01.x); fma2(acc[1][1], a01.y, b01.y);
            fma2(acc[1][2], a01.y, b23.x); fma2(acc[1][3], a01.y, b23.y);
            fma2(acc[2][0], a23.x, b01.x); fma2(acc[2][1], a23.x, b01.y);
            fma2(acc[2][2], a23.x, b23.x); fma2(acc[2][3], a23.x, b23.y);
            fma2(acc[3][0], a23.y, b01.x); fma2(acc[3][1], a23.y, b01.y);
            fma2(acc[3][2], a23.y, b23.x); fma2(acc[3][3], a23.y, b23.y);
        }
        __syncthreads();
    }

    const int col = n0 + tx * 8;
    #pragma unroll
    for (int i = 0; i < 4; i++) {
        int row = m0 + ty * 4 + i;
        float2 c0 = unpack2(acc[i][0]);
        float2 c1 = unpack2(acc[i][1]);
        float2 c2 = unpack2(acc[i][2]);
        float2 c3 = unpack2(acc[i][3]);
        float4 o0 = {c0.x, c0.y, c1.x, c1.y};
        float4 o1 = {c2.x, c2.y, c3.x, c3.y};
        *(float4*)(P + row * H2_ + col + 0) = o0;
        *(float4*)(P + row * H2_ + col + 4) = o1;
    }
}

// ---------------------------------------------------------------------------
// GEMM2 partials: Q[head][ks] = relu(sum_j H[head][j] + b1) @ W2-slice (raw).
// 64x64 tile, 128 thr, 4x8 micro. grid (2, 8, 8): z = head*4 + ks.
// ---------------------------------------------------------------------------
__global__ __launch_bounds__(128) void k_gemm2(
    const float* __restrict__ b1mu, const float* __restrict__ b1lv,
    const float* __restrict__ W2mu, const float* __restrict__ W2lv)
{
    const int  head = blockIdx.z >> 2;
    const int  ks   = blockIdx.z & 3;
    const float* Hb = &g_H[head][0][0];
    const float* b1 = head ? b1lv : b1mu;
    const float* W  = head ? W2lv : W2mu;
    float*       Q  = g_Q[head][ks];

    __shared__ __align__(16) u64   As2[16][66];
    __shared__ __align__(16) float Bs [16][68];

    const int tid = threadIdx.x;
    const int tx  = tid & 7;
    const int ty  = tid >> 3;
    const int m0  = blockIdx.y * 64;
    const int n0  = blockIdx.x * 64;

    const int arow = tid >> 1;
    const int ak   = (tid & 1) * 8;
    const int brow = tid >> 3;
    const int bcol = (tid & 7) * 8;

    const int kbase = ks * (H2_ / KS2);  // 128 per split
    const int abase = (m0 + arow) * H2_ + kbase + ak;
    const float* Wp = W + (kbase + brow) * YD + n0 + bcol;
    const size_t HS = (size_t)B_ * H2_;

    u64 acc[4][4] = {};

    const int k_iters = (H2_ / KS2) / 16;  // 8
    for (int it = 0; it < k_iters; it++) {
        // A fragment: sum 4 gemm1 partials + bias, relu
        {
            int off = abase + it * 16;
            float4 s_lo = *(const float4*)(b1 + kbase + ak + it * 16 + 0);
            float4 s_hi = *(const float4*)(b1 + kbase + ak + it * 16 + 4);
            #pragma unroll
            for (int j = 0; j < KS1; j++) {
                float4 p_lo = *(const float4*)(Hb + j * HS + off + 0);
                float4 p_hi = *(const float4*)(Hb + j * HS + off + 4);
                s_lo.x += p_lo.x; s_lo.y += p_lo.y; s_lo.z += p_lo.z; s_lo.w += p_lo.w;
                s_hi.x += p_hi.x; s_hi.y += p_hi.y; s_hi.z += p_hi.z; s_hi.w += p_hi.w;
            }
            float v0 = fmaxf(s_lo.x, 0.0f), v1 = fmaxf(s_lo.y, 0.0f);
            float v2 = fmaxf(s_lo.z, 0.0f), v3 = fmaxf(s_lo.w, 0.0f);
            float v4 = fmaxf(s_hi.x, 0.0f), v5 = fmaxf(s_hi.y, 0.0f);
            float v6 = fmaxf(s_hi.z, 0.0f), v7 = fmaxf(s_hi.w, 0.0f);
            As2[ak + 0][arow] = pack2(v0, v0);
            As2[ak + 1][arow] = pack2(v1, v1);
            As2[ak + 2][arow] = pack2(v2, v2);
            As2[ak + 3][arow] = pack2(v3, v3);
            As2[ak + 4][arow] = pack2(v4, v4);
            As2[ak + 5][arow] = pack2(v5, v5);
            As2[ak + 6][arow] = pack2(v6, v6);
            As2[ak + 7][arow] = pack2(v7, v7);
        }
        {
            float4 b_lo = *(const float4*)(Wp + it * 16 * YD + 0);
            float4 b_hi = *(const float4*)(Wp + it * 16 * YD + 4);
            *(float4*)(&Bs[brow][bcol + 0]) = b_lo;
            *(float4*)(&Bs[brow][bcol + 4]) = b_hi;
        }
        __syncthreads();

        #pragma unroll
        for (int kk = 0; kk < 16; kk++) {
            ulonglong2 a01 = *(const ulonglong2*)(&As2[kk][ty * 4 + 0]);
            ulonglong2 a23 = *(const ulonglong2*)(&As2[kk][ty * 4 + 2]);
            ulonglong2 b01 = *(const ulonglong2*)(&Bs[kk][tx * 8 + 0]);
            ulonglong2 b23 = *(const ulonglong2*)(&Bs[kk][tx * 8 + 4]);
            fma2(acc[0][0], a01.x, b01.x); fma2(acc[0][1], a01.x, b01.y);
            fma2(acc[0][2], a01.x, b23.x); fma2(acc[0][3], a01.x, b23.y);
            fma2(acc[1][0], a01.y, b01.x); fma2(acc[1][1], a01.y, b01.y);
            fma2(acc[1][2], a01.y, b23.x); fma2(acc[1][3], a01.y, b23.y);
            fma2(acc[2][0], a23.x, b01.x); fma2(acc[2][1], a23.x, b01.y);
            fma2(acc[2][2], a23.x, b23.x); fma2(acc[2][3], a23.x, b23.y);
            fma2(acc[3][0], a23.y, b01.x); fma2(acc[3][1], a23.y, b01.y);
            fma2(acc[3][2], a23.y, b23.x); fma2(acc[3][3], a23.y, b23.y);
        }
        __syncthreads();
    }

    const int col = n0 + tx * 8;
    #pragma unroll
    for (int i = 0; i < 4; i++) {
        int row = m0 + ty * 4 + i;
        float2 c0 = unpack2(acc[i][0]);
        float2 c1 = unpack2(acc[i][1]);
        float2 c2 = unpack2(acc[i][2]);
        float2 c3 = unpack2(acc[i][3]);
        float4 o0 = {c0.x, c0.y, c1.x, c1.y};
        float4 o1 = {c2.x, c2.y, c3.x, c3.y};
        *(float4*)(Q + row * YD + col + 0) = o0;
        *(float4*)(Q + row * YD + col + 4) = o1;
    }
}

// ---------------------------------------------------------------------------
// Kernel C: epilogue (bias+tanh+exp) + per-row reductions + final scalar.
// grid 128 x 128 thr; one warp per row (4 rows/block), last-block ticket.
//  mu = sum_j Qmu_j + b2mu;  lv = tanh(sum_j Qlv_j + b2lv);  iv = exp(-lv)
//  pos_i = sum_d [-0.5 (mu-y)^2 iv - 0.5 lv]
//  all_i = sum_d [-0.5 iv (Sy2 - 2 mu Sy + 512 mu^2) - 256 lv]
// negative == all_probs exactly in fp32 (511 + e^-20 == 511; log(B-1) cancels)
// ---------------------------------------------------------------------------
__global__ __launch_bounds__(128) void k_rows_final(
    const float* __restrict__ Y,
    const float* __restrict__ b2mu, const float* __restrict__ b2lv,
    float* __restrict__ out, int out_size)
{
    __shared__ double sSy[YD];
    __shared__ double sSy2[YD];
    __shared__ bool s_last;

    const int tid = threadIdx.x;

    {
        double s = 0.0, s2 = 0.0;
        #pragma unroll
        for (int p = 0; p < NPART; p++) { s += g_SyP[p][tid]; s2 += g_Sy2P[p][tid]; }
        sSy[tid] = s; sSy2[tid] = s2;
    }
    __syncthreads();

    const int lane = tid & 31;
    const int wid  = tid >> 5;
    const int i    = blockIdx.x * 4 + wid;

    double pos = 0.0, row = 0.0;
    #pragma unroll
    for (int q = 0; q < 4; q++) {
        int d = q * 32 + lane;
        int idx = i * YD + d;
        float muf = b2mu[d];
        float sf  = b2lv[d];
        #pragma unroll
        for (int j = 0; j < KS2; j++) {
            muf += g_Q[0][j][idx];
            sf  += g_Q[1][j][idx];
        }
        float lvf = tanhf(sf);
        float ivf = expf(-lvf);
        float yf  = Y[idx];

        float dmy = muf - yf;
        pos += (double)fmaf(-0.5f * dmy * dmy, ivf, -0.5f * lvf);

        double mu = (double)muf;
        double tq = fma(mu, fma(512.0, mu, -2.0 * sSy[d]), sSy2[d]);
        row = fma(-0.5 * (double)ivf, tq, row);
        row = fma(-256.0, (double)lvf, row);
    }
    #pragma unroll
    for (int off = 16; off > 0; off >>= 1) {
        pos += __shfl_down_sync(0xffffffffu, pos, off);
        row += __shfl_down_sync(0xffffffffu, row, off);
    }
    if (lane == 0) {
        g_pos_row[i] = pos;
        g_all_row[i] = row;
        __threadfence();
    }
    __syncthreads();

    if (tid == 0) {
        unsigned old = atomicAdd(&g_ctr, 1u);
        s_last = (old == gridDim.x - 1);
    }
    __syncthreads();
    if (!s_last) return;

    // ---- last block: deterministic final reduce over 512 rows ----
    double p0 = 0.0, a0 = 0.0;
    #pragma unroll
    for (int j = tid; j < B_; j += 128) {
        p0 += g_pos_row[j];
        a0 += g_all_row[j];
    }
    sSy[tid]  = p0;
    sSy2[tid] = a0;
    __syncthreads();
    #pragma unroll
    for (int s = 64; s > 0; s >>= 1) {
        if (tid < s) { sSy[tid] += sSy[tid + s]; sSy2[tid] += sSy2[tid + s]; }
        __syncthreads();
    }
    if (tid == 0) {
        double res = sSy[0] / 512.0 - sSy2[0] / (512.0 * 512.0);
        out[0] = (float)res;
        g_ctr = 0;  // reset for next graph replay
    }
    for (int k = tid + 1; k < out_size; k += 128) out[k] = 0.0f;
}

// ---------------------------------------------------------------------------
extern "C" void kernel_launch(void* const* d_in, const int* in_sizes, int n_in,
                              void* d_out, int out_size)
{
    const float* x   = (const float*)d_in[0];
    const float* y   = (const float*)d_in[1];
    const float* w1m = (const float*)d_in[2];
    const float* b1m = (const float*)d_in[3];
    const float* w2m = (const float*)d_in[4];
    const float* b2m = (const float*)d_in[5];
    const float* w1l = (const float*)d_in[6];
    const float* b1l = (const float*)d_in[7];
    const float* w2l = (const float*)d_in[8];
    const float* b2l = (const float*)d_in[9];

    k_gemm1<<<512 + NPART, 128>>>(x, y, w1m, w1l);

    dim3 g2(YD / 64, B_ / 64, 8);    // (2, 8, 8) = 128 blocks
    k_gemm2<<<g2, 128>>>(b1m, b1l, w2m, w2l);

    k_rows_final<<<B_ / 4, 128>>>(y, b2m, b2l, (float*)d_out, out_size);
}

// round 8
// speedup vs baseline: 1.6020x; 1.6020x over previous
#include <cuda_runtime.h>
#include <math.h>
#include <stdint.h>

#define B_  512
#define XD  768
#define YD  128
#define H2_ 512
#define NPART 16
#define KS1 4          // gemm1 K-split (768/4 = 192)

typedef unsigned long long u64;

__device__ float  g_H[2][KS1][B_ * H2_];   // gemm1 raw partials
__device__ float  g_Q[2][2][B_ * YD];      // gemm2 raw partials
__device__ double g_SyP [NPART][YD];
__device__ double g_Sy2P[NPART][YD];
__device__ double g_pos_row[B_];
__device__ double g_all_row[B_];
__device__ unsigned int g_ctr = 0;

// ---------------- f32x2 packed-FMA helpers (SIMT gemm2) ----------------
__device__ __forceinline__ u64 pack2(float lo, float hi) {
    u64 r; asm("mov.b64 %0, {%1, %2};" : "=l"(r) : "f"(lo), "f"(hi)); return r;
}
__device__ __forceinline__ void fma2(u64 &d, u64 a, u64 b) {
    asm("fma.rn.f32x2 %0, %1, %2, %0;" : "+l"(d) : "l"(a), "l"(b));
}
__device__ __forceinline__ float2 unpack2(u64 v) {
    float2 f; asm("mov.b64 {%0, %1}, %2;" : "=f"(f.x), "=f"(f.y) : "l"(v)); return f;
}

// ---------------- tf32 helpers ----------------
__device__ __forceinline__ float tf32r(float x) {
    float r; asm("cvt.rna.tf32.f32 %0, %1;" : "=f"(r) : "f"(x)); return r;
}
// D += A(16x8) * B(8x8), tf32 inputs, f32 accum
#define MMA8(c, A, B) \
    asm volatile("mma.sync.aligned.m16n8k8.row.col.f32.tf32.tf32.f32 " \
        "{%0,%1,%2,%3},{%4,%5,%6,%7},{%8,%9},{%0,%1,%2,%3};" \
        : "+f"((c)[0]), "+f"((c)[1]), "+f"((c)[2]), "+f"((c)[3]) \
        : "r"((A)[0]), "r"((A)[1]), "r"((A)[2]), "r"((A)[3]), \
          "r"((B)[0]), "r"((B)[1]))

// ---------------------------------------------------------------------------
// Kernel A: blocks 0..127 = GEMM1 partials via 3xTF32 HMMA (mma.sync),
//           blocks 128..143 = y column stats.
// Block: 128x128 tile, K=192 slice (12 chunks of BK=16), 256 thr, 8 warps
// (2M x 4N, warp tile 64x32). Fragments pre-arranged in smem by the loaders.
// ---------------------------------------------------------------------------
__global__ __launch_bounds__(256) void k_gemm1_mma(
    const float* __restrict__ X, const float* __restrict__ Y,
    const float* __restrict__ Wmu, const float* __restrict__ Wlv)
{
    const int b = blockIdx.x;
    if (b >= 128) {
        const int p = b - 128;
        const int d = threadIdx.x;
        if (d < YD) {
            const int j0 = p * (B_ / NPART);
            double sy0 = 0, sy1 = 0, s20 = 0, s21 = 0;
            #pragma unroll 4
            for (int j = j0; j < j0 + B_ / NPART; j += 2) {
                double v0 = (double)Y[j * YD + d], v1 = (double)Y[(j + 1) * YD + d];
                sy0 += v0; s20 = fma(v0, v0, s20);
                sy1 += v1; s21 = fma(v1, v1, s21);
            }
            g_SyP[p][d] = sy0 + sy1; g_Sy2P[p][d] = s20 + s21;
        }
        return;
    }

    // fragment-order staging: A[kstep][mtile(8)][lane(32)][slot(4)], B[kstep][ntile(16)][lane(32)][slot(2)]
    __shared__ __align__(16) float Ah[2 * 8 * 32 * 4];   // 8KB
    __shared__ __align__(16) float Al[2 * 8 * 32 * 4];
    __shared__ __align__(16) float Bh[2 * 16 * 32 * 2];  // 8KB
    __shared__ __align__(16) float Bl[2 * 16 * 32 * 2];

    const int head = b & 1;
    const int ks   = (b >> 1) & 3;
    const int t4   = b >> 3;               // 0..15
    const int m0   = (t4 >> 2) * 128;
    const int n0   = (t4 & 3) * 128;
    const int kb   = ks * 192;
    const float* W = head ? Wlv : Wmu;
    float* P       = &g_H[head][ks][0];

    const int tid  = threadIdx.x;
    const int wid  = tid >> 5;
    const int lane = tid & 31;
    const int wm   = wid >> 2;             // 0..1 (64-row band)
    const int wn   = wid & 3;              // 0..3 (32-col band)
    const int lg   = lane >> 2;            // groupID
    const int lt   = lane & 3;             // tid-in-group

    // ---- loader mappings ----
    // A: r = tid>>1 (row 0..127), kst = tid&1; loads k = kst*8 + 0..7
    const int ar  = tid >> 1, akst = tid & 1;
    const int amt = ar >> 4, ag = ar & 7, arh = (ar >> 3) & 1;
    const float* Xp = X + (size_t)(m0 + ar) * XD + kb + akst * 8;
    // B: bk = tid>>4 (k-row 0..15), nq = tid&15; loads n = nq*8 + 0..7
    const int bkr = tid >> 4, bnq = tid & 15;
    const int bt  = bkr & 3, bkh = (bkr >> 2) & 1, bkst = bkr >> 3;
    const float* Wp = W + (size_t)(kb + bkr) * H2_ + n0 + bnq * 8;

    float acc[4][4][4] = {};   // [mf][nf][4]

    float4 xa0 = *(const float4*)(Xp + 0);
    float4 xa1 = *(const float4*)(Xp + 4);
    float4 wb0 = *(const float4*)(Wp + 0);
    float4 wb1 = *(const float4*)(Wp + 4);

    for (int ch = 0; ch < 12; ch++) {
        // ---- stage A fragments (hi/lo) ----
        #pragma unroll
        for (int kh = 0; kh < 2; kh++) {
            float4 v = kh ? xa1 : xa0;
            float e[4] = {v.x, v.y, v.z, v.w};
            #pragma unroll
            for (int q = 0; q < 4; q++) {
                float hi = tf32r(e[q]), lo = e[q] - hi;
                int lam  = (ag * 4 + q) ^ (akst | (ag & 2));
                int idx  = (((akst * 8 + amt) * 32 + lam) * 4) + (arh + 2 * kh);
                Ah[idx] = hi; Al[idx] = lo;
            }
        }
        // ---- stage B fragments (hi/lo) ----
        #pragma unroll
        for (int nh = 0; nh < 2; nh++) {
            float4 v = nh ? wb1 : wb0;
            float e[4] = {v.x, v.y, v.z, v.w};
            #pragma unroll
            for (int q = 0; q < 4; q++) {
                float hi = tf32r(e[q]), lo = e[q] - hi;
                int gg   = nh * 4 + q;
                int lam  = (gg * 4 + bt) ^ (bnq & 15);
                int idx  = (((bkst * 16 + bnq) * 32 + lam) * 2) + bkh;
                Bh[idx] = hi; Bl[idx] = lo;
            }
        }
        __syncthreads();

        if (ch + 1 < 12) {
            xa0 = *(const float4*)(Xp + (ch + 1) * 16 + 0);
            xa1 = *(const float4*)(Xp + (ch + 1) * 16 + 4);
            wb0 = *(const float4*)(Wp + (size_t)(ch + 1) * 16 * H2_ + 0);
            wb1 = *(const float4*)(Wp + (size_t)(ch + 1) * 16 * H2_ + 4);
        }

        // ---- compute: 2 ksteps x (4 mf x 4 nf) x 3 MMAs ----
        #pragma unroll
        for (int kst = 0; kst < 2; kst++) {
            uint32_t Af[4][4], Afl[4][4];
            #pragma unroll
            for (int mf = 0; mf < 4; mf++) {
                int mt  = wm * 4 + mf;
                int lam = lane ^ (kst | ((lane >> 2) & 2));
                int idx = ((kst * 8 + mt) * 32 + lam) * 4;
                uint4 h = *(const uint4*)&Ah[idx];
                uint4 l = *(const uint4*)&Al[idx];
                Af [mf][0] = h.x; Af [mf][1] = h.y; Af [mf][2] = h.z; Af [mf][3] = h.w;
                Afl[mf][0] = l.x; Afl[mf][1] = l.y; Afl[mf][2] = l.z; Afl[mf][3] = l.w;
            }
            uint32_t Bf[4][2], Bfl[4][2];
            #pragma unroll
            for (int nf = 0; nf < 4; nf++) {
                int nt  = wn * 4 + nf;
                int lam = lane ^ (nt & 15);
                int idx = ((kst * 16 + nt) * 32 + lam) * 2;
                uint2 h = *(const uint2*)&Bh[idx];
                uint2 l = *(const uint2*)&Bl[idx];
                Bf [nf][0] = h.x; Bf [nf][1] = h.y;
                Bfl[nf][0] = l.x; Bfl[nf][1] = l.y;
            }
            #pragma unroll
            for (int mf = 0; mf < 4; mf++)
                #pragma unroll
                for (int nf = 0; nf < 4; nf++) {
                    MMA8(acc[mf][nf], Af[mf],  Bf[nf]);
                    MMA8(acc[mf][nf], Af[mf],  Bfl[nf]);
                    MMA8(acc[mf][nf], Afl[mf], Bf[nf]);
                }
        }
        __syncthreads();
    }

    // ---- epilogue: raw partial store ----
    #pragma unroll
    for (int mf = 0; mf < 4; mf++) {
        int row0 = m0 + wm * 64 + mf * 16 + lg;
        #pragma unroll
        for (int nf = 0; nf < 4; nf++) {
            int col = n0 + wn * 32 + nf * 8 + lt * 2;
            *(float2*)(P + (size_t)row0 * H2_ + col)       = make_float2(acc[mf][nf][0], acc[mf][nf][1]);
            *(float2*)(P + (size_t)(row0 + 8) * H2_ + col) = make_float2(acc[mf][nf][2], acc[mf][nf][3]);
        }
    }
}

// ---------------------------------------------------------------------------
// GEMM2 partials (proven SIMT): Q[head][ks] = relu(sum_j H_j + b1) @ W2-slice.
// BM=32, BN=64, BK=16, 256 thr, 2x4 micro FFMA2. grid (2,16,4).
// ---------------------------------------------------------------------------
__global__ __launch_bounds__(256) void k_gemm2(
    const float* __restrict__ b1mu, const float* __restrict__ b1lv,
    const float* __restrict__ W2mu, const float* __restrict__ W2lv)
{
    const int  head = blockIdx.z >> 1;
    const int  ks   = blockIdx.z & 1;
    const float* Hb = &g_H[head][0][0];
    const float* b1 = head ? b1lv : b1mu;
    const float* W  = head ? W2lv : W2mu;
    float*       Q  = g_Q[head][ks];
    const size_t HS = (size_t)B_ * H2_;

    __shared__ u64   As2[16][32];
    __shared__ float Bs [16][64];

    const int tid = threadIdx.x;
    const int tx  = tid & 15;
    const int ty  = tid >> 4;
    const int m0  = blockIdx.y * 32;
    const int n0  = blockIdx.x * 64;

    const int arow = tid >> 3;
    const int ak   = (tid & 7) << 1;
    const int brow = tid >> 4;
    const int bcol = (tid & 15) << 2;

    const int kbase = ks * (H2_ / 2);
    const int aoff  = (m0 + arow) * H2_ + kbase + ak;
    const float* b1p = b1 + kbase + ak;
    const float* Wp  = W + (kbase + brow) * YD + n0 + bcol;

    u64 acc[2][2] = {};

    float2 p0 = *(const float2*)(Hb + 0 * HS + aoff);
    float2 p1 = *(const float2*)(Hb + 1 * HS + aoff);
    float2 p2 = *(const float2*)(Hb + 2 * HS + aoff);
    float2 p3 = *(const float2*)(Hb + 3 * HS + aoff);
    float2 bv = *(const float2*)(b1p);
    float4 b4 = *(const float4*)(Wp);

    const int k_iters = H2_ / 2 / 16;  // 16
    for (int it = 0; it < k_iters; it++) {
        float ax = fmaxf(p0.x + p1.x + p2.x + p3.x + bv.x, 0.0f);
        float ay = fmaxf(p0.y + p1.y + p2.y + p3.y + bv.y, 0.0f);
        As2[ak + 0][arow] = pack2(ax, ax);
        As2[ak + 1][arow] = pack2(ay, ay);
        *(float4*)(&Bs[brow][bcol]) = b4;
        __syncthreads();

        if (it + 1 < k_iters) {
            p0 = *(const float2*)(Hb + 0 * HS + aoff + (it + 1) * 16);
            p1 = *(const float2*)(Hb + 1 * HS + aoff + (it + 1) * 16);
            p2 = *(const float2*)(Hb + 2 * HS + aoff + (it + 1) * 16);
            p3 = *(const float2*)(Hb + 3 * HS + aoff + (it + 1) * 16);
            bv = *(const float2*)(b1p + (it + 1) * 16);
            b4 = *(const float4*)(Wp + (it + 1) * 16 * YD);
        }

        #pragma unroll
        for (int kk = 0; kk < 16; kk++) {
            ulonglong2 aa = *(const ulonglong2*)(&As2[kk][ty * 2]);
            ulonglong2 bb = *(const ulonglong2*)(&Bs[kk][tx * 4]);
            fma2(acc[0][0], aa.x, bb.x); fma2(acc[0][1], aa.x, bb.y);
            fma2(acc[1][0], aa.y, bb.x); fma2(acc[1][1], aa.y, bb.y);
        }
        __syncthreads();
    }

    const int col = n0 + tx * 4;
    #pragma unroll
    for (int i = 0; i < 2; i++) {
        int row = m0 + ty * 2 + i;
        float2 c01 = unpack2(acc[i][0]);
        float2 c23 = unpack2(acc[i][1]);
        float4 o = {c01.x, c01.y, c23.x, c23.y};
        *(float4*)(Q + row * YD + col) = o;
    }
}

// ---------------------------------------------------------------------------
// Kernel C: epilogue + per-row reductions + final scalar (last-block ticket).
// negative == all_probs exactly in fp32 (511 + e^-20 == 511; log(B-1) cancels)
// ---------------------------------------------------------------------------
__global__ __launch_bounds__(128) void k_rows_final(
    const float* __restrict__ Y,
    const float* __restrict__ b2mu, const float* __restrict__ b2lv,
    float* __restrict__ out, int out_size)
{
    __shared__ double sSy[YD];
    __shared__ double sSy2[YD];
    __shared__ bool s_last;

    const int tid = threadIdx.x;
    {
        double s = 0.0, s2 = 0.0;
        #pragma unroll
        for (int p = 0; p < NPART; p++) { s += g_SyP[p][tid]; s2 += g_Sy2P[p][tid]; }
        sSy[tid] = s; sSy2[tid] = s2;
    }
    __syncthreads();

    const int lane = tid & 31;
    const int wid  = tid >> 5;
    const int i    = blockIdx.x * 4 + wid;

    double pos = 0.0, row = 0.0;
    #pragma unroll
    for (int q = 0; q < 4; q++) {
        int d = q * 32 + lane;
        int idx = i * YD + d;
        float muf = g_Q[0][0][idx] + g_Q[0][1][idx] + b2mu[d];
        float sf  = g_Q[1][0][idx] + g_Q[1][1][idx] + b2lv[d];
        float lvf = tanhf(sf);
        float ivf = expf(-lvf);
        float yf  = Y[idx];

        float dmy = muf - yf;
        pos += (double)fmaf(-0.5f * dmy * dmy, ivf, -0.5f * lvf);

        double mu = (double)muf;
        double tq = fma(mu, fma(512.0, mu, -2.0 * sSy[d]), sSy2[d]);
        row = fma(-0.5 * (double)ivf, tq, row);
        row = fma(-256.0, (double)lvf, row);
    }
    #pragma unroll
    for (int off = 16; off > 0; off >>= 1) {
        pos += __shfl_down_sync(0xffffffffu, pos, off);
        row += __shfl_down_sync(0xffffffffu, row, off);
    }
    if (lane == 0) {
        g_pos_row[i] = pos;
        g_all_row[i] = row;
        __threadfence();
    }
    __syncthreads();

    if (tid == 0) {
        unsigned old = atomicAdd(&g_ctr, 1u);
        s_last = (old == gridDim.x - 1);
    }
    __syncthreads();
    if (!s_last) return;

    double p0 = 0.0, a0 = 0.0;
    #pragma unroll
    for (int j = tid; j < B_; j += 128) { p0 += g_pos_row[j]; a0 += g_all_row[j]; }
    sSy[tid]  = p0;
    sSy2[tid] = a0;
    __syncthreads();
    #pragma unroll
    for (int s = 64; s > 0; s >>= 1) {
        if (tid < s) { sSy[tid] += sSy[tid + s]; sSy2[tid] += sSy2[tid + s]; }
        __syncthreads();
    }
    if (tid == 0) {
        out[0] = (float)(sSy[0] / 512.0 - sSy2[0] / (512.0 * 512.0));
        g_ctr = 0;
    }
    for (int k = tid + 1; k < out_size; k += 128) out[k] = 0.0f;
}

// ---------------------------------------------------------------------------
extern "C" void kernel_launch(void* const* d_in, const int* in_sizes, int n_in,
                              void* d_out, int out_size)
{
    const float* x   = (const float*)d_in[0];
    const float* y   = (const float*)d_in[1];
    const float* w1m = (const float*)d_in[2];
    const float* b1m = (const float*)d_in[3];
    const float* w2m = (const float*)d_in[4];
    const float* b2m = (const float*)d_in[5];
    const float* w1l = (const float*)d_in[6];
    const float* b1l = (const float*)d_in[7];
    const float* w2l = (const float*)d_in[8];
    const float* b2l = (const float*)d_in[9];

    k_gemm1_mma<<<128 + NPART, 256>>>(x, y, w1m, w1l);

    dim3 g2(YD / 64, B_ / 32, 4);   // (2, 16, 4) = 128 blocks
    k_gemm2<<<g2, 256>>>(b1m, b1l, w2m, w2l);

    k_rows_final<<<B_ / 4, 128>>>(y, b2m, b2l, (float*)d_out, out_size);
}

// round 9
// speedup vs baseline: 1.8835x; 1.1757x over previous
#include <cuda_runtime.h>
#include <math.h>
#include <stdint.h>

#define B_  512
#define XD  768
#define YD  128
#define H2_ 512
#define NPART 16
#define KS1 4          // gemm1 K-split (768/4 = 192)
#define KS2 8          // gemm2 K-split (512/8 = 64)

typedef unsigned long long u64;

__device__ float  g_H[2][KS1][B_ * H2_];   // gemm1 raw partials
__device__ float  g_Q[2][KS2][B_ * YD];    // gemm2 raw partials
__device__ double g_SyP [NPART][YD];
__device__ double g_Sy2P[NPART][YD];
__device__ double g_pos_row[B_];
__device__ double g_all_row[B_];
__device__ unsigned int g_ctr = 0;

// ---------------- tf32 helpers ----------------
__device__ __forceinline__ float tf32r(float x) {
    float r; asm("cvt.rna.tf32.f32 %0, %1;" : "=f"(r) : "f"(x)); return r;
}
// D += A(16x8) * B(8x8), tf32 inputs, f32 accum
#define MMA8(c, A, B) \
    asm volatile("mma.sync.aligned.m16n8k8.row.col.f32.tf32.tf32.f32 " \
        "{%0,%1,%2,%3},{%4,%5,%6,%7},{%8,%9},{%0,%1,%2,%3};" \
        : "+f"((c)[0]), "+f"((c)[1]), "+f"((c)[2]), "+f"((c)[3]) \
        : "r"((A)[0]), "r"((A)[1]), "r"((A)[2]), "r"((A)[3]), \
          "r"((B)[0]), "r"((B)[1]))

// ---------------------------------------------------------------------------
// Kernel A: blocks 0..127 = GEMM1 partials via 3xTF32 HMMA, double-buffered
// software pipeline (one sync per chunk). blocks 128..143 = y column stats.
// Block: 128x128 tile, K=192 slice, 12 chunks of BK=16, 256 thr, 8 warps
// (2M x 4N, warp tile 64x32). 64KB dynamic smem (2 buffers).
// ---------------------------------------------------------------------------
__global__ __launch_bounds__(256) void k_gemm1_mma(
    const float* __restrict__ X, const float* __restrict__ Y,
    const float* __restrict__ Wmu, const float* __restrict__ Wlv)
{
    const int b = blockIdx.x;
    if (b >= 128) {
        const int p = b - 128;
        const int d = threadIdx.x;
        if (d < YD) {
            const int j0 = p * (B_ / NPART);
            double sy0 = 0, sy1 = 0, s20 = 0, s21 = 0;
            #pragma unroll 4
            for (int j = j0; j < j0 + B_ / NPART; j += 2) {
                double v0 = (double)Y[j * YD + d], v1 = (double)Y[(j + 1) * YD + d];
                sy0 += v0; s20 = fma(v0, v0, s20);
                sy1 += v1; s21 = fma(v1, v1, s21);
            }
            g_SyP[p][d] = sy0 + sy1; g_Sy2P[p][d] = s20 + s21;
        }
        return;
    }

    // dynamic smem: Ah | Al | Bh | Bl, each double-buffered
    extern __shared__ float smem[];
    float* Ah = smem;                 // [2][2][8][32][4]  = 4096 floats
    float* Al = smem + 4096;
    float* Bh = smem + 8192;          // [2][2][16][32][2] = 4096 floats
    float* Bl = smem + 12288;

    const int head = b & 1;
    const int ks   = (b >> 1) & 3;
    const int t4   = b >> 3;               // 0..15
    const int m0   = (t4 >> 2) * 128;
    const int n0   = (t4 & 3) * 128;
    const int kb   = ks * 192;
    const float* W = head ? Wlv : Wmu;
    float* P       = &g_H[head][ks][0];

    const int tid  = threadIdx.x;
    const int wid  = tid >> 5;
    const int lane = tid & 31;
    const int wm   = wid >> 2;             // 0..1
    const int wn   = wid & 3;              // 0..3
    const int lg   = lane >> 2;
    const int lt   = lane & 3;

    // A loader: r = tid>>1 (0..127), kst = tid&1
    const int ar  = tid >> 1, akst = tid & 1;
    const int amt = ar >> 4, ag = ar & 7, arh = (ar >> 3) & 1;
    const float* Xp = X + (size_t)(m0 + ar) * XD + kb + akst * 8;
    // B loader: bkr = tid>>4 (0..15), bnq = tid&15
    const int bkr = tid >> 4, bnq = tid & 15;
    const int bt  = bkr & 3, bkh = (bkr >> 2) & 1, bkst = bkr >> 3;
    const float* Wp = W + (size_t)(kb + bkr) * H2_ + n0 + bnq * 8;

    float acc[4][4][4] = {};
    float4 xa0, xa1, wb0, wb1;

    #define G1_LOAD(ch) do { \
        xa0 = *(const float4*)(Xp + (ch) * 16 + 0); \
        xa1 = *(const float4*)(Xp + (ch) * 16 + 4); \
        wb0 = *(const float4*)(Wp + (size_t)(ch) * 16 * H2_ + 0); \
        wb1 = *(const float4*)(Wp + (size_t)(ch) * 16 * H2_ + 4); \
    } while (0)

    #define G1_STAGE(bf) do { \
        _Pragma("unroll") \
        for (int kh = 0; kh < 2; kh++) { \
            float4 v = kh ? xa1 : xa0; \
            float e[4] = {v.x, v.y, v.z, v.w}; \
            _Pragma("unroll") \
            for (int q = 0; q < 4; q++) { \
                float hi = tf32r(e[q]), lo = e[q] - hi; \
                int lam = (ag * 4 + q) ^ (akst | (ag & 2)); \
                int idx = (((((bf) * 2 + akst) * 8 + amt) * 32 + lam) * 4) + (arh + 2 * kh); \
                Ah[idx] = hi; Al[idx] = lo; \
            } \
        } \
        _Pragma("unroll") \
        for (int nh = 0; nh < 2; nh++) { \
            float4 v = nh ? wb1 : wb0; \
            float e[4] = {v.x, v.y, v.z, v.w}; \
            _Pragma("unroll") \
            for (int q = 0; q < 4; q++) { \
                float hi = tf32r(e[q]), lo = e[q] - hi; \
                int gg  = nh * 4 + q; \
                int lam = (gg * 4 + bt) ^ (bnq & 15); \
                int idx = (((((bf) * 2 + bkst) * 16 + bnq) * 32 + lam) * 2) + bkh; \
                Bh[idx] = hi; Bl[idx] = lo; \
            } \
        } \
    } while (0)

    // prologue
    G1_LOAD(0);
    G1_STAGE(0);
    G1_LOAD(1);
    __syncthreads();

    for (int ch = 0; ch < 12; ch++) {
        const int bfc = ch & 1;
        if (ch + 1 < 12) G1_STAGE((ch + 1) & 1);
        if (ch + 2 < 12) G1_LOAD(ch + 2);

        #pragma unroll
        for (int kst = 0; kst < 2; kst++) {
            uint32_t Af[4][4], Afl[4][4];
            #pragma unroll
            for (int mf = 0; mf < 4; mf++) {
                int mt  = wm * 4 + mf;
                int lam = lane ^ (kst | ((lane >> 2) & 2));
                int idx = (((bfc * 2 + kst) * 8 + mt) * 32 + lam) * 4;
                uint4 h = *(const uint4*)&Ah[idx];
                uint4 l = *(const uint4*)&Al[idx];
                Af [mf][0] = h.x; Af [mf][1] = h.y; Af [mf][2] = h.z; Af [mf][3] = h.w;
                Afl[mf][0] = l.x; Afl[mf][1] = l.y; Afl[mf][2] = l.z; Afl[mf][3] = l.w;
            }
            uint32_t Bf[4][2], Bfl[4][2];
            #pragma unroll
            for (int nf = 0; nf < 4; nf++) {
                int nt  = wn * 4 + nf;
                int lam = lane ^ (nt & 15);
                int idx = (((bfc * 2 + kst) * 16 + nt) * 32 + lam) * 2;
                uint2 h = *(const uint2*)&Bh[idx];
                uint2 l = *(const uint2*)&Bl[idx];
                Bf [nf][0] = h.x; Bf [nf][1] = h.y;
                Bfl[nf][0] = l.x; Bfl[nf][1] = l.y;
            }
            #pragma unroll
            for (int mf = 0; mf < 4; mf++)
                #pragma unroll
                for (int nf = 0; nf < 4; nf++) {
                    MMA8(acc[mf][nf], Af[mf],  Bf[nf]);
                    MMA8(acc[mf][nf], Af[mf],  Bfl[nf]);
                    MMA8(acc[mf][nf], Afl[mf], Bf[nf]);
                }
        }
        __syncthreads();
    }

    #pragma unroll
    for (int mf = 0; mf < 4; mf++) {
        int row0 = m0 + wm * 64 + mf * 16 + lg;
        #pragma unroll
        for (int nf = 0; nf < 4; nf++) {
            int col = n0 + wn * 32 + nf * 8 + lt * 2;
            *(float2*)(P + (size_t)row0 * H2_ + col)       = make_float2(acc[mf][nf][0], acc[mf][nf][1]);
            *(float2*)(P + (size_t)(row0 + 8) * H2_ + col) = make_float2(acc[mf][nf][2], acc[mf][nf][3]);
        }
    }
}

// ---------------------------------------------------------------------------
// GEMM2 via 3xTF32 HMMA: Q[head][ks] = relu(sum_j H_j + b1) @ W2[kslice].
// Block: 64x128 tile, K=64 slice (4 chunks of 16), 256 thr, 8 warps
// (2M x 4N, warp tile 32x32), double-buffered. grid 128 = 2 heads x 8 M x 8 K.
// ---------------------------------------------------------------------------
__global__ __launch_bounds__(256) void k_gemm2_mma(
    const float* __restrict__ b1mu, const float* __restrict__ b1lv,
    const float* __restrict__ W2mu, const float* __restrict__ W2lv)
{
    __shared__ __align__(16) float Ah[2 * 2 * 4 * 32 * 4];   // 8KB
    __shared__ __align__(16) float Al[2 * 2 * 4 * 32 * 4];
    __shared__ __align__(16) float Bh[2 * 2 * 16 * 32 * 2];  // 16KB
    __shared__ __align__(16) float Bl[2 * 2 * 16 * 32 * 2];

    const int b    = blockIdx.x;
    const int head = b & 1;
    const int ks   = (b >> 1) & 7;
    const int m0   = (b >> 4) * 64;
    const int kb   = ks * 64;
    const float* Hb = &g_H[head][0][0];
    const float* b1 = head ? b1lv : b1mu;
    const float* W  = head ? W2lv : W2mu;
    float*       Q  = g_Q[head][ks];
    const size_t HS = (size_t)B_ * H2_;

    const int tid  = threadIdx.x;
    const int wid  = tid >> 5;
    const int lane = tid & 31;
    const int wm   = wid >> 2;             // 0..1 (32-row band)
    const int wn   = wid & 3;              // 0..3 (32-col band)
    const int lg   = lane >> 2;
    const int lt   = lane & 3;

    // A loader: r = tid>>2 (0..63), akq = tid&3 -> k = akq*4+q
    const int ar = tid >> 2, akq = tid & 3;
    const int akst = akq >> 1, akh = akq & 1;
    const int amt = ar >> 4, ag = ar & 7, arh = (ar >> 3) & 1;
    const size_t aoff = (size_t)(m0 + ar) * H2_ + kb + akq * 4;
    // B loader: bkr = tid>>4, bnq = tid&15
    const int bkr = tid >> 4, bnq = tid & 15;
    const int bt  = bkr & 3, bkh = (bkr >> 2) & 1, bkst = bkr >> 3;
    const float* Wp = W + (size_t)(kb + bkr) * YD + bnq * 8;

    float acc[2][4][4] = {};
    float4 h0, h1, h2, h3, bv4, wb0, wb1;

    #define G2_LOAD(ch) do { \
        h0  = *(const float4*)(Hb + 0 * HS + aoff + (ch) * 16); \
        h1  = *(const float4*)(Hb + 1 * HS + aoff + (ch) * 16); \
        h2  = *(const float4*)(Hb + 2 * HS + aoff + (ch) * 16); \
        h3  = *(const float4*)(Hb + 3 * HS + aoff + (ch) * 16); \
        bv4 = *(const float4*)(b1 + kb + akq * 4 + (ch) * 16); \
        wb0 = *(const float4*)(Wp + (size_t)(ch) * 16 * YD + 0); \
        wb1 = *(const float4*)(Wp + (size_t)(ch) * 16 * YD + 4); \
    } while (0)

    #define G2_STAGE(bf) do { \
        float e[4]; \
        e[0] = fmaxf(h0.x + h1.x + h2.x + h3.x + bv4.x, 0.0f); \
        e[1] = fmaxf(h0.y + h1.y + h2.y + h3.y + bv4.y, 0.0f); \
        e[2] = fmaxf(h0.z + h1.z + h2.z + h3.z + bv4.z, 0.0f); \
        e[3] = fmaxf(h0.w + h1.w + h2.w + h3.w + bv4.w, 0.0f); \
        _Pragma("unroll") \
        for (int q = 0; q < 4; q++) { \
            float hi = tf32r(e[q]), lo = e[q] - hi; \
            int lam = (ag * 4 + q) ^ (akst | (ag & 2)); \
            int idx = (((((bf) * 2 + akst) * 4 + amt) * 32 + lam) * 4) + (arh + 2 * akh); \
            Ah[idx] = hi; Al[idx] = lo; \
        } \
        _Pragma("unroll") \
        for (int nh = 0; nh < 2; nh++) { \
            float4 v = nh ? wb1 : wb0; \
            float f[4] = {v.x, v.y, v.z, v.w}; \
            _Pragma("unroll") \
            for (int q = 0; q < 4; q++) { \
                float hi = tf32r(f[q]), lo = f[q] - hi; \
                int gg  = nh * 4 + q; \
                int lam = (gg * 4 + bt) ^ (bnq & 15); \
                int idx = (((((bf) * 2 + bkst) * 16 + bnq) * 32 + lam) * 2) + bkh; \
                Bh[idx] = hi; Bl[idx] = lo; \
            } \
        } \
    } while (0)

    G2_LOAD(0);
    G2_STAGE(0);
    G2_LOAD(1);
    __syncthreads();

    for (int ch = 0; ch < 4; ch++) {
        const int bfc = ch & 1;
        if (ch + 1 < 4) G2_STAGE((ch + 1) & 1);
        if (ch + 2 < 4) G2_LOAD(ch + 2);

        #pragma unroll
        for (int kst = 0; kst < 2; kst++) {
            uint32_t Af[2][4], Afl[2][4];
            #pragma unroll
            for (int mf = 0; mf < 2; mf++) {
                int mt  = wm * 2 + mf;
                int lam = lane ^ (kst | ((lane >> 2) & 2));
                int idx = (((bfc * 2 + kst) * 4 + mt) * 32 + lam) * 4;
                uint4 h = *(const uint4*)&Ah[idx];
                uint4 l = *(const uint4*)&Al[idx];
                Af [mf][0] = h.x; Af [mf][1] = h.y; Af [mf][2] = h.z; Af [mf][3] = h.w;
                Afl[mf][0] = l.x; Afl[mf][1] = l.y; Afl[mf][2] = l.z; Afl[mf][3] = l.w;
            }
            uint32_t Bf[4][2], Bfl[4][2];
            #pragma unroll
            for (int nf = 0; nf < 4; nf++) {
                int nt  = wn * 4 + nf;
                int lam = lane ^ (nt & 15);
                int idx = (((bfc * 2 + kst) * 16 + nt) * 32 + lam) * 2;
                uint2 h = *(const uint2*)&Bh[idx];
                uint2 l = *(const uint2*)&Bl[idx];
                Bf [nf][0] = h.x; Bf [nf][1] = h.y;
                Bfl[nf][0] = l.x; Bfl[nf][1] = l.y;
            }
            #pragma unroll
            for (int mf = 0; mf < 2; mf++)
                #pragma unroll
                for (int nf = 0; nf < 4; nf++) {
                    MMA8(acc[mf][nf], Af[mf],  Bf[nf]);
                    MMA8(acc[mf][nf], Af[mf],  Bfl[nf]);
                    MMA8(acc[mf][nf], Afl[mf], Bf[nf]);
                }
        }
        __syncthreads();
    }

    #pragma unroll
    for (int mf = 0; mf < 2; mf++) {
        int row0 = m0 + wm * 32 + mf * 16 + lg;
        #pragma unroll
        for (int nf = 0; nf < 4; nf++) {
            int col = (wn * 4 + nf) * 8 + lt * 2;
            *(float2*)(Q + (size_t)row0 * YD + col)       = make_float2(acc[mf][nf][0], acc[mf][nf][1]);
            *(float2*)(Q + (size_t)(row0 + 8) * YD + col) = make_float2(acc[mf][nf][2], acc[mf][nf][3]);
        }
    }
}

// ---------------------------------------------------------------------------
// Kernel C: epilogue + per-row reductions + final scalar (last-block ticket).
// negative == all_probs exactly in fp32 (511 + e^-20 == 511; log(B-1) cancels)
// ---------------------------------------------------------------------------
__global__ __launch_bounds__(128) void k_rows_final(
    const float* __restrict__ Y,
    const float* __restrict__ b2mu, const float* __restrict__ b2lv,
    float* __restrict__ out, int out_size)
{
    __shared__ double sSy[YD];
    __shared__ double sSy2[YD];
    __shared__ bool s_last;

    const int tid = threadIdx.x;
    {
        double s = 0.0, s2 = 0.0;
        #pragma unroll
        for (int p = 0; p < NPART; p++) { s += g_SyP[p][tid]; s2 += g_Sy2P[p][tid]; }
        sSy[tid] = s; sSy2[tid] = s2;
    }
    __syncthreads();

    const int lane = tid & 31;
    const int wid  = tid >> 5;
    const int i    = blockIdx.x * 4 + wid;

    double pos = 0.0, row = 0.0;
    #pragma unroll
    for (int q = 0; q < 4; q++) {
        int d = q * 32 + lane;
        int idx = i * YD + d;
        float muf = b2mu[d];
        float sf  = b2lv[d];
        #pragma unroll
        for (int j = 0; j < KS2; j++) {
            muf += g_Q[0][j][idx];
            sf  += g_Q[1][j][idx];
        }
        float lvf = tanhf(sf);
        float ivf = expf(-lvf);
        float yf  = Y[idx];

        float dmy = muf - yf;
        pos += (double)fmaf(-0.5f * dmy * dmy, ivf, -0.5f * lvf);

        double mu = (double)muf;
        double tq = fma(mu, fma(512.0, mu, -2.0 * sSy[d]), sSy2[d]);
        row = fma(-0.5 * (double)ivf, tq, row);
        row = fma(-256.0, (double)lvf, row);
    }
    #pragma unroll
    for (int off = 16; off > 0; off >>= 1) {
        pos += __shfl_down_sync(0xffffffffu, pos, off);
        row += __shfl_down_sync(0xffffffffu, row, off);
    }
    if (lane == 0) {
        g_pos_row[i] = pos;
        g_all_row[i] = row;
        __threadfence();
    }
    __syncthreads();

    if (tid == 0) {
        unsigned old = atomicAdd(&g_ctr, 1u);
        s_last = (old == gridDim.x - 1);
    }
    __syncthreads();
    if (!s_last) return;

    double p0 = 0.0, a0 = 0.0;
    #pragma unroll
    for (int j = tid; j < B_; j += 128) { p0 += g_pos_row[j]; a0 += g_all_row[j]; }
    sSy[tid]  = p0;
    sSy2[tid] = a0;
    __syncthreads();
    #pragma unroll
    for (int s = 64; s > 0; s >>= 1) {
        if (tid < s) { sSy[tid] += sSy[tid + s]; sSy2[tid] += sSy2[tid + s]; }
        __syncthreads();
    }
    if (tid == 0) {
        out[0] = (float)(sSy[0] / 512.0 - sSy2[0] / (512.0 * 512.0));
        g_ctr = 0;
    }
    for (int k = tid + 1; k < out_size; k += 128) out[k] = 0.0f;
}

// ---------------------------------------------------------------------------
extern "C" void kernel_launch(void* const* d_in, const int* in_sizes, int n_in,
                              void* d_out, int out_size)
{
    const float* x   = (const float*)d_in[0];
    const float* y   = (const float*)d_in[1];
    const float* w1m = (const float*)d_in[2];
    const float* b1m = (const float*)d_in[3];
    const float* w2m = (const float*)d_in[4];
    const float* b2m = (const float*)d_in[5];
    const float* w1l = (const float*)d_in[6];
    const float* b1l = (const float*)d_in[7];
    const float* w2l = (const float*)d_in[8];
    const float* b2l = (const float*)d_in[9];

    static int smem_set = 0;
    if (!smem_set) {
        cudaFuncSetAttribute(k_gemm1_mma, cudaFuncAttributeMaxDynamicSharedMemorySize, 65536);
        smem_set = 1;
    }

    k_gemm1_mma<<<128 + NPART, 256, 65536>>>(x, y, w1m, w1l);
    k_gemm2_mma<<<128, 256>>>(b1m, b1l, w2m, w2l);
    k_rows_final<<<B_ / 4, 128>>>(y, b2m, b2l, (float*)d_out, out_size);
}